// round 15
// baseline (speedup 1.0000x reference)
#include <cuda_runtime.h>
#include <cuda_fp16.h>
#include <cstdint>

// ---------------- problem constants ----------------
#define T_TOK 4096      // B*S
#define HDIM  1024
#define HFF   4096
#define NEXP  8
#define WELEM (NEXP * HFF * HDIM)     // 33554432 elems per weight tensor

// ---------------- GEMM tiling (fp16 m16n8k16) ----------------
#define BM 128
#define BN 256
#define KC 64                          // K elems per pipeline chunk (4 k-steps of 16)
#define NSTAGE 3
#define ROWB 144                       // padded smem row stride in BYTES (128B data + 16B)
#define AB0  (BM * ROWB)               // 18432 B: A region size per stage
#define STAGE_BYTES ((BM + BN) * ROWB) // 55296 B
#define DYN_SMEM (NSTAGE * STAGE_BYTES) // 165888 B -> 1 CTA/SM
#define NTHR 256

// ---------------- device scratch (no allocations allowed) ----------------
__device__ int    g_cnt[NEXP];
__device__ int    g_list[NEXP * T_TOK];
__device__ float  g_gval[NEXP * T_TOK];
__device__ int    g_i32flag;
__device__ __align__(16) __half g_xh[T_TOK * HDIM];      // fp16 x
__device__ __align__(16) __half g_w1h[WELEM];            // fp16 W1
__device__ __align__(16) __half g_w2h[WELEM];            // fp16 W2
// fp16 H rows; padded by BM rows so tail tiles of the last expert can be READ
// (never written) without OOB.
__device__ __align__(16) __half g_hbuf[(size_t)(T_TOK * 2 + BM) * HFF];

// ---------------- helpers ----------------
__device__ __forceinline__ uint32_t smem_u32(const void* p) {
    uint32_t a;
    asm("{ .reg .u64 t; cvta.to.shared.u64 t, %1; cvt.u32.u64 %0, t; }" : "=r"(a) : "l"(p));
    return a;
}
__device__ __forceinline__ float gelu_t(float x) {
    float t = tanhf(0.7978845608028654f * (x + 0.044715f * x * x * x));
    return 0.5f * x * (1.0f + t);
}

#define MMA_F16(c, a, b)                                                    \
    asm volatile(                                                           \
        "mma.sync.aligned.m16n8k16.row.col.f32.f16.f16.f32 "                \
        "{%0,%1,%2,%3}, {%4,%5,%6,%7}, {%8,%9}, {%0,%1,%2,%3};"             \
        : "+f"((c)[0]), "+f"((c)[1]), "+f"((c)[2]), "+f"((c)[3])            \
        : "r"((a)[0]), "r"((a)[1]), "r"((a)[2]), "r"((a)[3]),               \
          "r"((b)[0]), "r"((b)[1]))

#define CP_ASYNC16(dst, src)                                                \
    asm volatile("cp.async.cg.shared.global [%0], [%1], 16;"                \
                 :: "r"(dst), "l"(src) : "memory")
#define CP_COMMIT()  asm volatile("cp.async.commit_group;" ::: "memory")

#define LDSM_X4(r0, r1, r2, r3, addr)                                       \
    asm volatile("ldmatrix.sync.aligned.m8n8.x4.shared.b16 {%0,%1,%2,%3}, [%4];" \
        : "=r"(r0), "=r"(r1), "=r"(r2), "=r"(r3) : "r"(addr))

// ---------------- small kernels (validated rounds 3-14) ----------------
__global__ void k_zero(float4* out4, int n4) {
    int i = blockIdx.x * blockDim.x + threadIdx.x;
    if (i < n4) out4[i] = make_float4(0.f, 0.f, 0.f, 0.f);
    if (i < NEXP) g_cnt[i] = 0;
    if (i == 0) g_i32flag = 0;
}

__global__ void k_detect(const int* __restrict__ idx32) {
    int i = blockIdx.x * blockDim.x + threadIdx.x;
    int v = 0;
    for (int j = i; j < (T_TOK * 2) / 2; j += gridDim.x * blockDim.x)
        v |= idx32[2 * j + 1];
    if (v) atomicOr(&g_i32flag, 1);
}

__global__ void k_gate(const void* __restrict__ idx_raw, const float* __restrict__ probs) {
    int t = blockIdx.x * blockDim.x + threadIdx.x;
    if (t >= T_TOK) return;
    int e0, e1;
    if (g_i32flag) {
        const int* p = (const int*)idx_raw;
        e0 = p[2 * t]; e1 = p[2 * t + 1];
    } else {
        const long long* p = (const long long*)idx_raw;
        e0 = (int)p[2 * t]; e1 = (int)p[2 * t + 1];
    }
    float p0 = probs[2 * t], p1 = probs[2 * t + 1];
    if (e0 == e1) { p0 = fmaxf(p0, p1); e1 = -1; }   // max over k dedups
    if ((unsigned)e0 < NEXP) {
        int pos = atomicAdd(&g_cnt[e0], 1);
        g_list[e0 * T_TOK + pos] = t;
        g_gval[e0 * T_TOK + pos] = p0;
    }
    if ((unsigned)e1 < NEXP) {
        int pos = atomicAdd(&g_cnt[e1], 1);
        g_list[e1 * T_TOK + pos] = t;
        g_gval[e1 * T_TOK + pos] = p1;
    }
}

// ---------------- prep: fp32 -> fp16 copies of W1, W2, x --------------------
__global__ void k_prepw(const float4* __restrict__ w1, const float4* __restrict__ w2) {
    const int stride = gridDim.x * blockDim.x;
    __half2* o1 = (__half2*)g_w1h;
    __half2* o2 = (__half2*)g_w2h;
    for (int j = blockIdx.x * blockDim.x + threadIdx.x; j < WELEM / 4; j += stride) {
        float4 a = w1[j];
        o1[2 * j]     = __floats2half2_rn(a.x, a.y);
        o1[2 * j + 1] = __floats2half2_rn(a.z, a.w);
        float4 b = w2[j];
        o2[2 * j]     = __floats2half2_rn(b.x, b.y);
        o2[2 * j + 1] = __floats2half2_rn(b.z, b.w);
    }
}
__global__ void k_prepx(const float4* __restrict__ x) {
    const int stride = gridDim.x * blockDim.x;
    __half2* ox = (__half2*)g_xh;
    for (int j = blockIdx.x * blockDim.x + threadIdx.x;
         j < (T_TOK * HDIM) / 4; j += stride) {
        float4 v = x[j];
        ox[2 * j]     = __floats2half2_rn(v.x, v.y);
        ox[2 * j + 1] = __floats2half2_rn(v.z, v.w);
    }
}

// ---------------- grouped GEMM: fp16, 128x256 tile, 64x64 warp tile ---------
// G1: H[base+m, n] = h16( gelu( xh[list[m]] . W1h[e][n] ) ),  KDIM = HDIM
// G2: out[list[m]] += gate[m] * ( H[base+m] . W2h[e][n] ),     KDIM = HFF
extern __shared__ char dynsm[];

template <int KDIM, bool IS_G1>
__global__ __launch_bounds__(NTHR, 1)
void k_gemm(float* __restrict__ outp) {
    const int e = blockIdx.z;
    const int cnt = g_cnt[e];
    const int m0 = blockIdx.x * BM;
    if (m0 >= cnt) return;
    const int n0 = blockIdx.y * BN;
    int base = 0;
#pragma unroll
    for (int i = 0; i < NEXP; ++i) base += (i < e) ? g_cnt[i] : 0;

    const int tid = threadIdx.x;
    const int lane = tid & 31, warp = tid >> 5;
    const int wm = warp & 1, wn = warp >> 1;     // 2 x 4 warp grid, 64x64 tiles
    const int g = lane >> 2, tq = lane & 3;
    const uint32_t sb = smem_u32(dynsm);

    const __half* Bw = IS_G1 ? g_w1h : g_w2h;

    // ---- cp.async mapping: 12 granules/thread (A rows i=0..3, B rows i=4..11)
    // row handled at step i: A r = (tid>>3) + 32*i ; B r = (tid>>3) + 32*(i-4)
    const int r0 = tid >> 3, gc = tid & 7;
    const __half* srcA[4];
#pragma unroll
    for (int i = 0; i < 4; ++i) {
        int m = m0 + r0 + 32 * i;
        if (IS_G1) {
            int tok = (m < cnt) ? g_list[e * T_TOK + m] : g_list[e * T_TOK];
            srcA[i] = g_xh + (size_t)tok * KDIM + gc * 8;
        } else {
            srcA[i] = g_hbuf + (size_t)(base + m) * KDIM + gc * 8;   // padded buffer
        }
    }
    const __half* srcB = Bw + (size_t)e * HFF * HDIM +
                         (size_t)(n0 + r0) * KDIM + gc * 8;
    const uint32_t dstA0 = (uint32_t)(r0 * ROWB + gc * 16);
    const uint32_t dstB0 = (uint32_t)(AB0 + r0 * ROWB + gc * 16);

    auto issue = [&](int kt, int buf) {
        uint32_t b = sb + buf * STAGE_BYTES;
        const int ko = kt * KC;
#pragma unroll
        for (int i = 0; i < 4; ++i)
            CP_ASYNC16(b + dstA0 + (uint32_t)(i * 32 * ROWB), srcA[i] + ko);
#pragma unroll
        for (int i = 0; i < 8; ++i)
            CP_ASYNC16(b + dstB0 + (uint32_t)(i * 32 * ROWB),
                       srcB + (size_t)i * 32 * KDIM + ko);
        CP_COMMIT();
    };

    // ---- ldmatrix per-thread base offsets (bytes within a stage) ----
    const uint32_t aoff =
        (uint32_t)((wm * 64 + (lane & 15)) * ROWB + 16 * (lane >> 4));
    const uint32_t boff = (uint32_t)(AB0 +
        (wn * 64 + 8 * (lane >> 4) + (lane & 7)) * ROWB + 16 * ((lane >> 3) & 1));

    float acc[4][8][4];
#pragma unroll
    for (int mi = 0; mi < 4; ++mi)
#pragma unroll
        for (int ni = 0; ni < 8; ++ni)
#pragma unroll
            for (int ci = 0; ci < 4; ++ci) acc[mi][ni][ci] = 0.f;

    constexpr int KT = KDIM / KC;
    issue(0, 0);
    issue(1, 1);

    uint32_t aF[2][4][4], bF[2][8][2];
    auto ldfrag = [&](int pb, uint32_t stg, int ks) {
        const uint32_t ko = (uint32_t)(ks * 32);   // 16 fp16 = 32 B per k-step
#pragma unroll
        for (int mi = 0; mi < 4; ++mi)
            LDSM_X4(aF[pb][mi][0], aF[pb][mi][1], aF[pb][mi][2], aF[pb][mi][3],
                    stg + aoff + (uint32_t)(mi * 16 * ROWB) + ko);
#pragma unroll
        for (int p = 0; p < 4; ++p)
            LDSM_X4(bF[pb][2 * p][0], bF[pb][2 * p][1],
                    bF[pb][2 * p + 1][0], bF[pb][2 * p + 1][1],
                    stg + boff + (uint32_t)(p * 16 * ROWB) + ko);
    };

    for (int kt = 0; kt < KT; ++kt) {
        // after this wait, committed-but-pending must exclude group kt
        if (kt < KT - 1) asm volatile("cp.async.wait_group 1;" ::: "memory");
        else             asm volatile("cp.async.wait_group 0;" ::: "memory");
        __syncthreads();   // stage kt landed for ALL threads; buffer (kt-1)%3 free
        if (kt + 2 < KT) issue(kt + 2, (kt + 2) % 3);

        const uint32_t stg = sb + (kt % 3) * STAGE_BYTES;
        ldfrag(0, stg, 0);
#pragma unroll
        for (int ks = 0; ks < 4; ++ks) {
            const int pb = ks & 1;
            if (ks < 3) ldfrag(pb ^ 1, stg, ks + 1);  // hide LDS under MMAs
#pragma unroll
            for (int mi = 0; mi < 4; ++mi)
#pragma unroll
                for (int ni = 0; ni < 8; ++ni)
                    MMA_F16(acc[mi][ni], aF[pb][mi], bF[pb][ni]);
        }
        // no bottom barrier: buffer kt%3 is only rewritten after the top
        // barrier of iteration kt+1, which all warps reach post-compute.
    }

    // ---- epilogue ----
#pragma unroll
    for (int mi = 0; mi < 4; ++mi) {
        const int mA = m0 + wm * 64 + mi * 16 + g;
        const int mB = mA + 8;
        if (IS_G1) {
            __half* rowA = g_hbuf + (size_t)(base + mA) * HFF;
            __half* rowB = g_hbuf + (size_t)(base + mB) * HFF;
#pragma unroll
            for (int ni = 0; ni < 8; ++ni) {
                const int col = n0 + wn * 64 + ni * 8 + 2 * tq;
                if (mA < cnt)
                    *(__half2*)(rowA + col) = __floats2half2_rn(
                        gelu_t(acc[mi][ni][0]), gelu_t(acc[mi][ni][1]));
                if (mB < cnt)
                    *(__half2*)(rowB + col) = __floats2half2_rn(
                        gelu_t(acc[mi][ni][2]), gelu_t(acc[mi][ni][3]));
            }
        } else {
            int tokA = 0, tokB = 0;
            float gA = 0.f, gB = 0.f;
            if (mA < cnt) { tokA = g_list[e * T_TOK + mA]; gA = g_gval[e * T_TOK + mA]; }
            if (mB < cnt) { tokB = g_list[e * T_TOK + mB]; gB = g_gval[e * T_TOK + mB]; }
#pragma unroll
            for (int ni = 0; ni < 8; ++ni) {
                const int col = n0 + wn * 64 + ni * 8 + 2 * tq;
                if (mA < cnt) {
                    atomicAdd(&outp[(size_t)tokA * HDIM + col],     gA * acc[mi][ni][0]);
                    atomicAdd(&outp[(size_t)tokA * HDIM + col + 1], gA * acc[mi][ni][1]);
                }
                if (mB < cnt) {
                    atomicAdd(&outp[(size_t)tokB * HDIM + col],     gB * acc[mi][ni][2]);
                    atomicAdd(&outp[(size_t)tokB * HDIM + col + 1], gB * acc[mi][ni][3]);
                }
            }
        }
    }
}

// ---------------- launch ----------------
extern "C" void kernel_launch(void* const* d_in, const int* in_sizes, int n_in,
                              void* d_out, int out_size) {
    const float* x     = (const float*)d_in[0];
    const float* probs = (const float*)d_in[1];
    const void*  idx   = d_in[2];
    const float* W1    = (const float*)d_in[3];
    const float* W2    = (const float*)d_in[4];
    float* out = (float*)d_out;

    cudaFuncSetAttribute(k_gemm<HDIM, true>,
                         cudaFuncAttributeMaxDynamicSharedMemorySize, DYN_SMEM);
    cudaFuncSetAttribute(k_gemm<HFF, false>,
                         cudaFuncAttributeMaxDynamicSharedMemorySize, DYN_SMEM);

    const int n4 = out_size / 4;
    k_zero<<<(n4 + 255) / 256, 256>>>((float4*)out, n4);
    k_detect<<<32, 256>>>((const int*)idx);
    k_gate<<<(T_TOK + 255) / 256, 256>>>(idx, probs);
    k_prepw<<<2048, 256>>>((const float4*)W1, (const float4*)W2);
    k_prepx<<<256, 256>>>((const float4*)x);

    dim3 g1(T_TOK / BM, HFF / BN, NEXP);   // (32, 16, 8); tail CTAs self-prune
    k_gemm<HDIM, true><<<g1, NTHR, DYN_SMEM>>>(nullptr);

    dim3 g2(T_TOK / BM, HDIM / BN, NEXP);  // (32, 4, 8)
    k_gemm<HFF, false><<<g2, NTHR, DYN_SMEM>>>(out);
}

// round 16
// speedup vs baseline: 1.0644x; 1.0644x over previous
#include <cuda_runtime.h>
#include <cuda_fp16.h>
#include <cstdint>

// ---------------- problem constants ----------------
#define T_TOK 4096      // B*S
#define HDIM  1024
#define HFF   4096
#define NEXP  8
#define WELEM (NEXP * HFF * HDIM)     // 33554432 elems per weight tensor

// ---------------- GEMM tiling (fp16 m16n8k16) ----------------
#define BM 128
#define BN 128
#define KC 64                          // K elems per pipeline chunk (4 k-steps of 16)
#define NSTAGE 3
#define ROWB 144                       // padded smem row stride in BYTES (128B data + 16B)
#define AB0  (BM * ROWB)               // 18432 B: A region size per stage
#define STAGE_BYTES ((BM + BN) * ROWB) // 36864 B
#define DYN_SMEM (NSTAGE * STAGE_BYTES) // 110592 B -> 2 CTAs/SM
#define NTHR 128                       // 4 warps, 64x64 warp tiles (2x2)

// ---------------- device scratch (no allocations allowed) ----------------
__device__ int    g_cnt[NEXP];
__device__ int    g_list[NEXP * T_TOK];
__device__ float  g_gval[NEXP * T_TOK];
__device__ int    g_i32flag;
__device__ __align__(16) __half g_xh[T_TOK * HDIM];      // fp16 x
__device__ __align__(16) __half g_w1h[WELEM];            // fp16 W1
__device__ __align__(16) __half g_w2h[WELEM];            // fp16 W2
// fp16 H rows; padded by BM rows so tail tiles of the last expert can be READ
// (never written) without OOB.
__device__ __align__(16) __half g_hbuf[(size_t)(T_TOK * 2 + BM) * HFF];

// ---------------- helpers ----------------
__device__ __forceinline__ uint32_t smem_u32(const void* p) {
    uint32_t a;
    asm("{ .reg .u64 t; cvta.to.shared.u64 t, %1; cvt.u32.u64 %0, t; }" : "=r"(a) : "l"(p));
    return a;
}
__device__ __forceinline__ float gelu_t(float x) {
    float t = tanhf(0.7978845608028654f * (x + 0.044715f * x * x * x));
    return 0.5f * x * (1.0f + t);
}

#define MMA_F16(c, a, b)                                                    \
    asm volatile(                                                           \
        "mma.sync.aligned.m16n8k16.row.col.f32.f16.f16.f32 "                \
        "{%0,%1,%2,%3}, {%4,%5,%6,%7}, {%8,%9}, {%0,%1,%2,%3};"             \
        : "+f"((c)[0]), "+f"((c)[1]), "+f"((c)[2]), "+f"((c)[3])            \
        : "r"((a)[0]), "r"((a)[1]), "r"((a)[2]), "r"((a)[3]),               \
          "r"((b)[0]), "r"((b)[1]))

#define CP_ASYNC16(dst, src)                                                \
    asm volatile("cp.async.cg.shared.global [%0], [%1], 16;"                \
                 :: "r"(dst), "l"(src) : "memory")
#define CP_COMMIT()  asm volatile("cp.async.commit_group;" ::: "memory")

#define LDSM_X4(r0, r1, r2, r3, addr)                                       \
    asm volatile("ldmatrix.sync.aligned.m8n8.x4.shared.b16 {%0,%1,%2,%3}, [%4];" \
        : "=r"(r0), "=r"(r1), "=r"(r2), "=r"(r3) : "r"(addr))

// ---------------- small kernels (validated rounds 3-15) ----------------
__global__ void k_zero(float4* out4, int n4) {
    int i = blockIdx.x * blockDim.x + threadIdx.x;
    if (i < n4) out4[i] = make_float4(0.f, 0.f, 0.f, 0.f);
    if (i < NEXP) g_cnt[i] = 0;
    if (i == 0) g_i32flag = 0;
}

__global__ void k_detect(const int* __restrict__ idx32) {
    int i = blockIdx.x * blockDim.x + threadIdx.x;
    int v = 0;
    for (int j = i; j < (T_TOK * 2) / 2; j += gridDim.x * blockDim.x)
        v |= idx32[2 * j + 1];
    if (v) atomicOr(&g_i32flag, 1);
}

__global__ void k_gate(const void* __restrict__ idx_raw, const float* __restrict__ probs) {
    int t = blockIdx.x * blockDim.x + threadIdx.x;
    if (t >= T_TOK) return;
    int e0, e1;
    if (g_i32flag) {
        const int* p = (const int*)idx_raw;
        e0 = p[2 * t]; e1 = p[2 * t + 1];
    } else {
        const long long* p = (const long long*)idx_raw;
        e0 = (int)p[2 * t]; e1 = (int)p[2 * t + 1];
    }
    float p0 = probs[2 * t], p1 = probs[2 * t + 1];
    if (e0 == e1) { p0 = fmaxf(p0, p1); e1 = -1; }   // max over k dedups
    if ((unsigned)e0 < NEXP) {
        int pos = atomicAdd(&g_cnt[e0], 1);
        g_list[e0 * T_TOK + pos] = t;
        g_gval[e0 * T_TOK + pos] = p0;
    }
    if ((unsigned)e1 < NEXP) {
        int pos = atomicAdd(&g_cnt[e1], 1);
        g_list[e1 * T_TOK + pos] = t;
        g_gval[e1 * T_TOK + pos] = p1;
    }
}

// ---------------- prep: fp32 -> fp16 copies of W1, W2, x --------------------
__global__ void k_prepw(const float4* __restrict__ w1, const float4* __restrict__ w2) {
    const int stride = gridDim.x * blockDim.x;
    __half2* o1 = (__half2*)g_w1h;
    __half2* o2 = (__half2*)g_w2h;
    for (int j = blockIdx.x * blockDim.x + threadIdx.x; j < WELEM / 4; j += stride) {
        float4 a = w1[j];
        o1[2 * j]     = __floats2half2_rn(a.x, a.y);
        o1[2 * j + 1] = __floats2half2_rn(a.z, a.w);
        float4 b = w2[j];
        o2[2 * j]     = __floats2half2_rn(b.x, b.y);
        o2[2 * j + 1] = __floats2half2_rn(b.z, b.w);
    }
}
__global__ void k_prepx(const float4* __restrict__ x) {
    const int stride = gridDim.x * blockDim.x;
    __half2* ox = (__half2*)g_xh;
    for (int j = blockIdx.x * blockDim.x + threadIdx.x;
         j < (T_TOK * HDIM) / 4; j += stride) {
        float4 v = x[j];
        ox[2 * j]     = __floats2half2_rn(v.x, v.y);
        ox[2 * j + 1] = __floats2half2_rn(v.z, v.w);
    }
}

// ---------------- grouped GEMM: fp16, 128x128 tile, 4 warps of 64x64 --------
// G1: H[base+m, n] = h16( gelu( xh[list[m]] . W1h[e][n] ) ),  KDIM = HDIM
// G2: out[list[m]] += gate[m] * ( H[base+m] . W2h[e][n] ),     KDIM = HFF
extern __shared__ char dynsm[];

template <int KDIM, bool IS_G1>
__global__ __launch_bounds__(NTHR, 2)
void k_gemm(float* __restrict__ outp) {
    const int e = blockIdx.z;
    const int cnt = g_cnt[e];
    const int m0 = blockIdx.x * BM;
    if (m0 >= cnt) return;
    const int n0 = blockIdx.y * BN;
    int base = 0;
#pragma unroll
    for (int i = 0; i < NEXP; ++i) base += (i < e) ? g_cnt[i] : 0;

    const int tid = threadIdx.x;
    const int lane = tid & 31, warp = tid >> 5;
    const int wm = warp & 1, wn = warp >> 1;     // 2 x 2 warp grid, 64x64 tiles
    const int g = lane >> 2, tq = lane & 3;
    const uint32_t sb = smem_u32(dynsm);

    const __half* Bw = IS_G1 ? g_w1h : g_w2h;

    // ---- cp.async mapping: 16 granules/thread (A rows i=0..7, B rows i=8..15)
    // 128 threads: tid>>3 in 0..15, row at step i = (tid>>3) + 16*i
    const int r0 = tid >> 3, gc = tid & 7;
    const __half* srcA[8];
#pragma unroll
    for (int i = 0; i < 8; ++i) {
        int m = m0 + r0 + 16 * i;
        if (IS_G1) {
            int tok = (m < cnt) ? g_list[e * T_TOK + m] : g_list[e * T_TOK];
            srcA[i] = g_xh + (size_t)tok * KDIM + gc * 8;
        } else {
            srcA[i] = g_hbuf + (size_t)(base + m) * KDIM + gc * 8;   // padded buffer
        }
    }
    const __half* srcB = Bw + (size_t)e * HFF * HDIM +
                         (size_t)(n0 + r0) * KDIM + gc * 8;
    const uint32_t dstA0 = (uint32_t)(r0 * ROWB + gc * 16);
    const uint32_t dstB0 = (uint32_t)(AB0 + r0 * ROWB + gc * 16);

    auto issue = [&](int kt, int buf) {
        uint32_t b = sb + buf * STAGE_BYTES;
        const int ko = kt * KC;
#pragma unroll
        for (int i = 0; i < 8; ++i)
            CP_ASYNC16(b + dstA0 + (uint32_t)(i * 16 * ROWB), srcA[i] + ko);
#pragma unroll
        for (int i = 0; i < 8; ++i)
            CP_ASYNC16(b + dstB0 + (uint32_t)(i * 16 * ROWB),
                       srcB + (size_t)i * 16 * KDIM + ko);
        CP_COMMIT();
    };

    // ---- ldmatrix per-thread base offsets (bytes within a stage) ----
    const uint32_t aoff =
        (uint32_t)((wm * 64 + (lane & 15)) * ROWB + 16 * (lane >> 4));
    const uint32_t boff = (uint32_t)(AB0 +
        (wn * 64 + 8 * (lane >> 4) + (lane & 7)) * ROWB + 16 * ((lane >> 3) & 1));

    float acc[4][8][4];
#pragma unroll
    for (int mi = 0; mi < 4; ++mi)
#pragma unroll
        for (int ni = 0; ni < 8; ++ni)
#pragma unroll
            for (int ci = 0; ci < 4; ++ci) acc[mi][ni][ci] = 0.f;

    constexpr int KT = KDIM / KC;
    issue(0, 0);
    issue(1, 1);

    uint32_t aF[2][4][4], bF[2][8][2];
    auto ldfrag = [&](int pb, uint32_t stg, int ks) {
        const uint32_t ko = (uint32_t)(ks * 32);   // 16 fp16 = 32 B per k-step
#pragma unroll
        for (int mi = 0; mi < 4; ++mi)
            LDSM_X4(aF[pb][mi][0], aF[pb][mi][1], aF[pb][mi][2], aF[pb][mi][3],
                    stg + aoff + (uint32_t)(mi * 16 * ROWB) + ko);
#pragma unroll
        for (int p = 0; p < 4; ++p)
            LDSM_X4(bF[pb][2 * p][0], bF[pb][2 * p][1],
                    bF[pb][2 * p + 1][0], bF[pb][2 * p + 1][1],
                    stg + boff + (uint32_t)(p * 16 * ROWB) + ko);
    };

    for (int kt = 0; kt < KT; ++kt) {
        // after this wait, committed-but-pending must exclude group kt
        if (kt < KT - 1) asm volatile("cp.async.wait_group 1;" ::: "memory");
        else             asm volatile("cp.async.wait_group 0;" ::: "memory");
        __syncthreads();   // stage kt landed for ALL threads; buffer (kt-1)%3 free
        if (kt + 2 < KT) issue(kt + 2, (kt + 2) % 3);

        const uint32_t stg = sb + (kt % 3) * STAGE_BYTES;
        ldfrag(0, stg, 0);
#pragma unroll
        for (int ks = 0; ks < 4; ++ks) {
            const int pb = ks & 1;
            if (ks < 3) ldfrag(pb ^ 1, stg, ks + 1);  // hide LDS under MMAs
#pragma unroll
            for (int mi = 0; mi < 4; ++mi)
#pragma unroll
                for (int ni = 0; ni < 8; ++ni)
                    MMA_F16(acc[mi][ni], aF[pb][mi], bF[pb][ni]);
        }
        // no bottom barrier: buffer kt%3 is only rewritten after the top
        // barrier of iteration kt+1, which all warps reach post-compute.
    }

    // ---- epilogue ----
#pragma unroll
    for (int mi = 0; mi < 4; ++mi) {
        const int mA = m0 + wm * 64 + mi * 16 + g;
        const int mB = mA + 8;
        if (IS_G1) {
            __half* rowA = g_hbuf + (size_t)(base + mA) * HFF;
            __half* rowB = g_hbuf + (size_t)(base + mB) * HFF;
#pragma unroll
            for (int ni = 0; ni < 8; ++ni) {
                const int col = n0 + wn * 64 + ni * 8 + 2 * tq;
                if (mA < cnt)
                    *(__half2*)(rowA + col) = __floats2half2_rn(
                        gelu_t(acc[mi][ni][0]), gelu_t(acc[mi][ni][1]));
                if (mB < cnt)
                    *(__half2*)(rowB + col) = __floats2half2_rn(
                        gelu_t(acc[mi][ni][2]), gelu_t(acc[mi][ni][3]));
            }
        } else {
            int tokA = 0, tokB = 0;
            float gA = 0.f, gB = 0.f;
            if (mA < cnt) { tokA = g_list[e * T_TOK + mA]; gA = g_gval[e * T_TOK + mA]; }
            if (mB < cnt) { tokB = g_list[e * T_TOK + mB]; gB = g_gval[e * T_TOK + mB]; }
#pragma unroll
            for (int ni = 0; ni < 8; ++ni) {
                const int col = n0 + wn * 64 + ni * 8 + 2 * tq;
                if (mA < cnt) {
                    atomicAdd(&outp[(size_t)tokA * HDIM + col],     gA * acc[mi][ni][0]);
                    atomicAdd(&outp[(size_t)tokA * HDIM + col + 1], gA * acc[mi][ni][1]);
                }
                if (mB < cnt) {
                    atomicAdd(&outp[(size_t)tokB * HDIM + col],     gB * acc[mi][ni][2]);
                    atomicAdd(&outp[(size_t)tokB * HDIM + col + 1], gB * acc[mi][ni][3]);
                }
            }
        }
    }
}

// ---------------- launch ----------------
extern "C" void kernel_launch(void* const* d_in, const int* in_sizes, int n_in,
                              void* d_out, int out_size) {
    const float* x     = (const float*)d_in[0];
    const float* probs = (const float*)d_in[1];
    const void*  idx   = d_in[2];
    const float* W1    = (const float*)d_in[3];
    const float* W2    = (const float*)d_in[4];
    float* out = (float*)d_out;

    cudaFuncSetAttribute(k_gemm<HDIM, true>,
                         cudaFuncAttributeMaxDynamicSharedMemorySize, DYN_SMEM);
    cudaFuncSetAttribute(k_gemm<HFF, false>,
                         cudaFuncAttributeMaxDynamicSharedMemorySize, DYN_SMEM);

    const int n4 = out_size / 4;
    k_zero<<<(n4 + 255) / 256, 256>>>((float4*)out, n4);
    k_detect<<<32, 256>>>((const int*)idx);
    k_gate<<<(T_TOK + 255) / 256, 256>>>(idx, probs);
    k_prepw<<<2048, 256>>>((const float4*)W1, (const float4*)W2);
    k_prepx<<<256, 256>>>((const float4*)x);

    dim3 g1(T_TOK / BM, HFF / BN, NEXP);   // (32, 32, 8); tail CTAs self-prune
    k_gemm<HDIM, true><<<g1, NTHR, DYN_SMEM>>>(nullptr);

    dim3 g2(T_TOK / BM, HDIM / BN, NEXP);  // (32, 8, 8)
    k_gemm<HFF, false><<<g2, NTHR, DYN_SMEM>>>(out);
}

// round 17
// speedup vs baseline: 1.1510x; 1.0813x over previous
#include <cuda_runtime.h>
#include <cuda_fp16.h>
#include <cstdint>

// ---------------- problem constants ----------------
#define T_TOK 4096      // B*S
#define HDIM  1024
#define HFF   4096
#define NEXP  8
#define WELEM (NEXP * HFF * HDIM)     // 33554432 elems per weight tensor

// ---------------- GEMM tiling (fp16 m16n8k16) — R14-proven config ----------
#define BM 128
#define BN 128
#define KC 64                          // K elems per pipeline chunk (4 k-steps of 16)
#define NSTAGE 3
#define ROWB 144                       // padded smem row stride in BYTES (128B data + 16B)
#define AB0  (BM * ROWB)               // 18432 B: A region size per stage
#define STAGE_BYTES ((BM + BN) * ROWB) // 36864 B
#define DYN_SMEM (NSTAGE * STAGE_BYTES) // 110592 B -> 2 CTAs/SM
#define NTHR 256                       // 8 warps, 64x32 warp tiles (2x4)

// ---------------- device scratch (no allocations allowed) ----------------
__device__ int    g_cnt[NEXP];
__device__ int    g_list[NEXP * T_TOK];
__device__ float  g_gval[NEXP * T_TOK];
__device__ int    g_i32flag;
__device__ __align__(16) __half g_xh[T_TOK * HDIM];      // fp16 x
__device__ __align__(16) __half g_w1h[WELEM];            // fp16 W1
__device__ __align__(16) __half g_w2h[WELEM];            // fp16 W2
// fp16 H rows; padded by BM rows so tail tiles of the last expert can be READ
// (never written) without OOB.
__device__ __align__(16) __half g_hbuf[(size_t)(T_TOK * 2 + BM) * HFF];

// ---------------- helpers ----------------
__device__ __forceinline__ uint32_t smem_u32(const void* p) {
    uint32_t a;
    asm("{ .reg .u64 t; cvta.to.shared.u64 t, %1; cvt.u32.u64 %0, t; }" : "=r"(a) : "l"(p));
    return a;
}
__device__ __forceinline__ float gelu_t(float x) {
    float t = tanhf(0.7978845608028654f * (x + 0.044715f * x * x * x));
    return 0.5f * x * (1.0f + t);
}

#define MMA_F16(c, a, b)                                                    \
    asm volatile(                                                           \
        "mma.sync.aligned.m16n8k16.row.col.f32.f16.f16.f32 "                \
        "{%0,%1,%2,%3}, {%4,%5,%6,%7}, {%8,%9}, {%0,%1,%2,%3};"             \
        : "+f"((c)[0]), "+f"((c)[1]), "+f"((c)[2]), "+f"((c)[3])            \
        : "r"((a)[0]), "r"((a)[1]), "r"((a)[2]), "r"((a)[3]),               \
          "r"((b)[0]), "r"((b)[1]))

#define CP_ASYNC16(dst, src)                                                \
    asm volatile("cp.async.cg.shared.global [%0], [%1], 16;"                \
                 :: "r"(dst), "l"(src) : "memory")
#define CP_COMMIT()  asm volatile("cp.async.commit_group;" ::: "memory")

#define LDSM_X4(r0, r1, r2, r3, addr)                                       \
    asm volatile("ldmatrix.sync.aligned.m8n8.x4.shared.b16 {%0,%1,%2,%3}, [%4];" \
        : "=r"(r0), "=r"(r1), "=r"(r2), "=r"(r3) : "r"(addr))

// ---------------- small kernels (validated rounds 3-16) ----------------
__global__ void k_zero(float4* out4, int n4) {
    int i = blockIdx.x * blockDim.x + threadIdx.x;
    if (i < n4) out4[i] = make_float4(0.f, 0.f, 0.f, 0.f);
    if (i < NEXP) g_cnt[i] = 0;
    if (i == 0) g_i32flag = 0;
}

__global__ void k_detect(const int* __restrict__ idx32) {
    int i = blockIdx.x * blockDim.x + threadIdx.x;
    int v = 0;
    for (int j = i; j < (T_TOK * 2) / 2; j += gridDim.x * blockDim.x)
        v |= idx32[2 * j + 1];
    if (v) atomicOr(&g_i32flag, 1);
}

__global__ void k_gate(const void* __restrict__ idx_raw, const float* __restrict__ probs) {
    int t = blockIdx.x * blockDim.x + threadIdx.x;
    if (t >= T_TOK) return;
    int e0, e1;
    if (g_i32flag) {
        const int* p = (const int*)idx_raw;
        e0 = p[2 * t]; e1 = p[2 * t + 1];
    } else {
        const long long* p = (const long long*)idx_raw;
        e0 = (int)p[2 * t]; e1 = (int)p[2 * t + 1];
    }
    float p0 = probs[2 * t], p1 = probs[2 * t + 1];
    if (e0 == e1) { p0 = fmaxf(p0, p1); e1 = -1; }   // max over k dedups
    if ((unsigned)e0 < NEXP) {
        int pos = atomicAdd(&g_cnt[e0], 1);
        g_list[e0 * T_TOK + pos] = t;
        g_gval[e0 * T_TOK + pos] = p0;
    }
    if ((unsigned)e1 < NEXP) {
        int pos = atomicAdd(&g_cnt[e1], 1);
        g_list[e1 * T_TOK + pos] = t;
        g_gval[e1 * T_TOK + pos] = p1;
    }
}

// ---------------- prep: fp32 -> fp16 copies of W1, W2, x (one launch) ------
__global__ void k_prep(const float4* __restrict__ w1, const float4* __restrict__ w2,
                       const float4* __restrict__ x) {
    const int stride = gridDim.x * blockDim.x;
    __half2* o1 = (__half2*)g_w1h;
    __half2* o2 = (__half2*)g_w2h;
    __half2* ox = (__half2*)g_xh;
    const int i0 = blockIdx.x * blockDim.x + threadIdx.x;
    for (int j = i0; j < WELEM / 4; j += stride) {
        float4 a = w1[j];
        o1[2 * j]     = __floats2half2_rn(a.x, a.y);
        o1[2 * j + 1] = __floats2half2_rn(a.z, a.w);
        float4 b = w2[j];
        o2[2 * j]     = __floats2half2_rn(b.x, b.y);
        o2[2 * j + 1] = __floats2half2_rn(b.z, b.w);
    }
    for (int j = i0; j < (T_TOK * HDIM) / 4; j += stride) {
        float4 v = x[j];
        ox[2 * j]     = __floats2half2_rn(v.x, v.y);
        ox[2 * j + 1] = __floats2half2_rn(v.z, v.w);
    }
}

// ---------------- grouped GEMM: fp16, 128x128 tile, 8 warps of 64x32 --------
// G1 (NSPLIT=1): H[base+m, n] = h16( gelu( xh[list[m]] . W1h[e][n] ) )
// G2 (NSPLIT=2): out[list[m]] += gate[m] * ( H[base+m] . W2h[e][n] ), K split
//                across blockIdx.z parity; both halves atomicAdd into out.
extern __shared__ char dynsm[];

template <int KDIM, bool IS_G1, int NSPLIT>
__global__ __launch_bounds__(NTHR, 2)
void k_gemm(float* __restrict__ outp) {
    const int e = blockIdx.z / NSPLIT;
    const int split = blockIdx.z % NSPLIT;
    const int koff = split * (KDIM / NSPLIT);
    const int cnt = g_cnt[e];
    const int m0 = blockIdx.x * BM;
    if (m0 >= cnt) return;
    const int n0 = blockIdx.y * BN;
    int base = 0;
#pragma unroll
    for (int i = 0; i < NEXP; ++i) base += (i < e) ? g_cnt[i] : 0;

    const int tid = threadIdx.x;
    const int lane = tid & 31, warp = tid >> 5;
    const int wm = warp & 1, wn = warp >> 1;     // 2 x 4 warp grid, 64x32 tiles
    const int g = lane >> 2, tq = lane & 3;
    const uint32_t sb = smem_u32(dynsm);

    const __half* Bw = IS_G1 ? g_w1h : g_w2h;

    // ---- cp.async mapping: 8 granules/thread (A rows i=0..3, B rows i=4..7)
    const int r0 = tid >> 3, gc = tid & 7;
    const __half* srcA[4];
#pragma unroll
    for (int i = 0; i < 4; ++i) {
        int m = m0 + r0 + 32 * i;
        if (IS_G1) {
            int tok = (m < cnt) ? g_list[e * T_TOK + m] : g_list[e * T_TOK];
            srcA[i] = g_xh + (size_t)tok * KDIM + koff + gc * 8;
        } else {
            srcA[i] = g_hbuf + (size_t)(base + m) * KDIM + koff + gc * 8;  // padded
        }
    }
    const __half* srcB = Bw + (size_t)e * HFF * HDIM +
                         (size_t)(n0 + r0) * KDIM + koff + gc * 8;
    const uint32_t dstA0 = (uint32_t)(r0 * ROWB + gc * 16);
    const uint32_t dstB0 = (uint32_t)(AB0 + r0 * ROWB + gc * 16);

    auto issue = [&](int kt, int buf) {
        uint32_t b = sb + buf * STAGE_BYTES;
        const int ko = kt * KC;
#pragma unroll
        for (int i = 0; i < 4; ++i)
            CP_ASYNC16(b + dstA0 + (uint32_t)(i * 32 * ROWB), srcA[i] + ko);
#pragma unroll
        for (int i = 0; i < 4; ++i)
            CP_ASYNC16(b + dstB0 + (uint32_t)(i * 32 * ROWB),
                       srcB + (size_t)i * 32 * KDIM + ko);
        CP_COMMIT();
    };

    // ---- ldmatrix per-thread base offsets (bytes within a stage) ----
    const uint32_t aoff =
        (uint32_t)((wm * 64 + (lane & 15)) * ROWB + 16 * (lane >> 4));
    const uint32_t boff = (uint32_t)(AB0 +
        (wn * 32 + 8 * (lane >> 4) + (lane & 7)) * ROWB + 16 * ((lane >> 3) & 1));

    float acc[4][4][4];
#pragma unroll
    for (int mi = 0; mi < 4; ++mi)
#pragma unroll
        for (int ni = 0; ni < 4; ++ni)
#pragma unroll
            for (int ci = 0; ci < 4; ++ci) acc[mi][ni][ci] = 0.f;

    constexpr int KT = KDIM / NSPLIT / KC;
    issue(0, 0);
    issue(1, 1);

    uint32_t aF[2][4][4], bF[2][4][2];
    auto ldfrag = [&](int pb, uint32_t stg, int ks) {
        const uint32_t ko = (uint32_t)(ks * 32);   // 16 fp16 = 32 B per k-step
#pragma unroll
        for (int mi = 0; mi < 4; ++mi)
            LDSM_X4(aF[pb][mi][0], aF[pb][mi][1], aF[pb][mi][2], aF[pb][mi][3],
                    stg + aoff + (uint32_t)(mi * 16 * ROWB) + ko);
        LDSM_X4(bF[pb][0][0], bF[pb][0][1], bF[pb][1][0], bF[pb][1][1],
                stg + boff + ko);
        LDSM_X4(bF[pb][2][0], bF[pb][2][1], bF[pb][3][0], bF[pb][3][1],
                stg + boff + (uint32_t)(16 * ROWB) + ko);
    };

    for (int kt = 0; kt < KT; ++kt) {
        // after this wait, committed-but-pending must exclude group kt
        if (kt < KT - 1) asm volatile("cp.async.wait_group 1;" ::: "memory");
        else             asm volatile("cp.async.wait_group 0;" ::: "memory");
        __syncthreads();   // stage kt landed for ALL threads; buffer (kt-1)%3 free
        if (kt + 2 < KT) issue(kt + 2, (kt + 2) % 3);

        const uint32_t stg = sb + (kt % 3) * STAGE_BYTES;
        ldfrag(0, stg, 0);
#pragma unroll
        for (int ks = 0; ks < 4; ++ks) {
            const int pb = ks & 1;
            if (ks < 3) ldfrag(pb ^ 1, stg, ks + 1);  // hide LDS under MMAs
#pragma unroll
            for (int mi = 0; mi < 4; ++mi)
#pragma unroll
                for (int ni = 0; ni < 4; ++ni)
                    MMA_F16(acc[mi][ni], aF[pb][mi], bF[pb][ni]);
        }
        // no bottom barrier: buffer kt%3 is only rewritten after the top
        // barrier of iteration kt+1, which all warps reach post-compute.
    }

    // ---- epilogue ----
#pragma unroll
    for (int mi = 0; mi < 4; ++mi) {
        const int mA = m0 + wm * 64 + mi * 16 + g;
        const int mB = mA + 8;
        if (IS_G1) {
            __half* rowA = g_hbuf + (size_t)(base + mA) * HFF;
            __half* rowB = g_hbuf + (size_t)(base + mB) * HFF;
#pragma unroll
            for (int ni = 0; ni < 4; ++ni) {
                const int col = n0 + wn * 32 + ni * 8 + 2 * tq;
                if (mA < cnt)
                    *(__half2*)(rowA + col) = __floats2half2_rn(
                        gelu_t(acc[mi][ni][0]), gelu_t(acc[mi][ni][1]));
                if (mB < cnt)
                    *(__half2*)(rowB + col) = __floats2half2_rn(
                        gelu_t(acc[mi][ni][2]), gelu_t(acc[mi][ni][3]));
            }
        } else {
            int tokA = 0, tokB = 0;
            float gA = 0.f, gB = 0.f;
            if (mA < cnt) { tokA = g_list[e * T_TOK + mA]; gA = g_gval[e * T_TOK + mA]; }
            if (mB < cnt) { tokB = g_list[e * T_TOK + mB]; gB = g_gval[e * T_TOK + mB]; }
#pragma unroll
            for (int ni = 0; ni < 4; ++ni) {
                const int col = n0 + wn * 32 + ni * 8 + 2 * tq;
                if (mA < cnt) {
                    atomicAdd(&outp[(size_t)tokA * HDIM + col],     gA * acc[mi][ni][0]);
                    atomicAdd(&outp[(size_t)tokA * HDIM + col + 1], gA * acc[mi][ni][1]);
                }
                if (mB < cnt) {
                    atomicAdd(&outp[(size_t)tokB * HDIM + col],     gB * acc[mi][ni][2]);
                    atomicAdd(&outp[(size_t)tokB * HDIM + col + 1], gB * acc[mi][ni][3]);
                }
            }
        }
    }
}

// ---------------- launch ----------------
extern "C" void kernel_launch(void* const* d_in, const int* in_sizes, int n_in,
                              void* d_out, int out_size) {
    const float* x     = (const float*)d_in[0];
    const float* probs = (const float*)d_in[1];
    const void*  idx   = d_in[2];
    const float* W1    = (const float*)d_in[3];
    const float* W2    = (const float*)d_in[4];
    float* out = (float*)d_out;

    cudaFuncSetAttribute(k_gemm<HDIM, true, 1>,
                         cudaFuncAttributeMaxDynamicSharedMemorySize, DYN_SMEM);
    cudaFuncSetAttribute(k_gemm<HFF, false, 2>,
                         cudaFuncAttributeMaxDynamicSharedMemorySize, DYN_SMEM);

    const int n4 = out_size / 4;
    k_zero<<<(n4 + 255) / 256, 256>>>((float4*)out, n4);
    k_detect<<<32, 256>>>((const int*)idx);
    k_gate<<<(T_TOK + 255) / 256, 256>>>(idx, probs);
    k_prep<<<2048, 256>>>((const float4*)W1, (const float4*)W2, (const float4*)x);

    dim3 g1(T_TOK / BM, HFF / BN, NEXP);       // (32, 32, 8); tails self-prune
    k_gemm<HDIM, true, 1><<<g1, NTHR, DYN_SMEM>>>(nullptr);

    dim3 g2(T_TOK / BM, HDIM / BN, NEXP * 2);  // (32, 8, 16): split-K=2
    k_gemm<HFF, false, 2><<<g2, NTHR, DYN_SMEM>>>(out);
}